// round 15
// baseline (speedup 1.0000x reference)
#include <cuda_runtime.h>
#include <cuda_fp16.h>
#include <cstdint>

#define T_TREES 100
#define NN      31
#define D       256
#define BATCH   8192
#define NU      16
#define NLEAF   32
#define NC      64

#define MROWS   1664              // 13 * 128 (1600 used, rest zero)
#define KA      256
#define TAU8    2.0f              // int8 ambiguity band (~10 sigma)
#define TAU16   0.05f             // fp16 ambiguity band (~8 sigma, validated)

// ---------------- static scratch ----------------
__device__ __align__(256) __half g_A[MROWS * KA];     // fp16 W (refine tier)
__device__ __align__(256) __half g_B[BATCH * D];      // fp16 X (refine tier)
__device__ __align__(256) char   g_A8[MROWS * D];     // int8 W
__device__ __align__(256) char   g_B8[BATCH * D];     // int8 X
__device__ float g_sw[MROWS];                         // per-W-row scale (max/127)
__device__ float g_sx[BATCH];                         // per-X-row scale
__device__ uint8_t g_leaf[T_TREES * BATCH];

// ---------------- helpers ----------------
__device__ __forceinline__ uint32_t smem_u32(const void* p) {
    uint32_t a;
    asm("{ .reg .u64 t; cvta.to.shared.u64 t, %1; cvt.u32.u64 %0, t; }"
        : "=r"(a) : "l"(p));
    return a;
}
__device__ __forceinline__ void cp16(uint32_t dst, const void* src) {
    asm volatile("cp.async.cg.shared.global [%0], [%1], 16;\n" :: "r"(dst), "l"(src));
}
__device__ __forceinline__ void cp_commit() { asm volatile("cp.async.commit_group;\n"); }
template <int N> __device__ __forceinline__ void cp_wait() {
    asm volatile("cp.async.wait_group %0;\n" :: "n"(N));
}
__device__ __forceinline__ void ldsm4(uint32_t* r, uint32_t addr) {
    asm volatile("ldmatrix.sync.aligned.m8n8.x4.shared.b16 {%0,%1,%2,%3}, [%4];"
        : "=r"(r[0]), "=r"(r[1]), "=r"(r[2]), "=r"(r[3]) : "r"(addr));
}
__device__ __forceinline__ void mma_s8(int* d, const uint32_t* a, const uint32_t* b) {
    asm volatile(
        "mma.sync.aligned.m16n8k32.row.col.s32.s8.s8.s32 "
        "{%0,%1,%2,%3}, {%4,%5,%6,%7}, {%8,%9}, {%0,%1,%2,%3};"
        : "+r"(d[0]), "+r"(d[1]), "+r"(d[2]), "+r"(d[3])
        : "r"(a[0]), "r"(a[1]), "r"(a[2]), "r"(a[3]), "r"(b[0]), "r"(b[1]));
}

// exact fp32 dot (final tier; validated)
__device__ __noinline__ float exact_dot(const float* __restrict__ node_w,
                                        const float* __restrict__ x,
                                        int tree, int node, int sample) {
    const float4* wp = (const float4*)(node_w + (size_t)(tree * NN + node) * D);
    const float4* xp = (const float4*)(x + (size_t)sample * D);
    float a0 = 0.f, a1 = 0.f, a2 = 0.f, a3 = 0.f;
    for (int i = 0; i < D / 4; i++) {
        float4 wv = wp[i], xv = xp[i];
        a0 += wv.x * xv.x; a1 += wv.y * xv.y;
        a2 += wv.z * xv.z; a3 += wv.w * xv.w;
    }
    return (a0 + a1) + (a2 + a3);
}

// fp16 dot from packed globals (middle tier; thread-local, latency-parallel)
__device__ __noinline__ float dot16(int arow, int sample) {
    const uint4* wp = (const uint4*)(g_A + (size_t)arow * KA);
    const uint4* xp = (const uint4*)(g_B + (size_t)sample * D);
    float acc = 0.f;
#pragma unroll 8
    for (int i = 0; i < 32; i++) {
        uint4 wv = wp[i], xv = xp[i];
        const __half2* wh = (const __half2*)&wv;
        const __half2* xh = (const __half2*)&xv;
#pragma unroll
        for (int j = 0; j < 4; j++) {
            float2 wf = __half22float2(wh[j]);
            float2 xf = __half22float2(xh[j]);
            acc += wf.x * xf.x + wf.y * xf.y;
        }
    }
    return acc;
}

// ---------------- merged pack kernel (scale + fp16 + int8 in one pass) -------
// W part: 416 blocks x 4 rows; X part: 2048 blocks x 4 rows. 64 thr (2 warps)
// per row; row-max via warp shfl + 2-warp smem exchange, then quantize.
#define PACKW_BLKS (MROWS / 4)            // 416
#define PACKX_BLKS (BATCH / 4)            // 2048
__device__ __forceinline__ char q8(float v, float inv) {
    int q = __float2int_rn(v * inv);
    q = max(-127, min(127, q));
    return (char)q;
}
__global__ void k_pack(const float* __restrict__ node_w, const float* __restrict__ x) {
    __shared__ float wmax[8];
    const int tid  = threadIdx.x;
    const int warp = tid >> 5, lane = tid & 31;
    const int k = (tid & 63) * 4;
    const int grp = tid >> 6;              // row group 0..3

    float4 w = make_float4(0.f, 0.f, 0.f, 0.f);
    int row;
    bool isW = blockIdx.x < PACKW_BLKS;
    if (isW) {
        row = blockIdx.x * 4 + grp;
        int tree = row >> 4;
        if (tree < T_TREES)
            w = *(const float4*)(node_w + (size_t)(tree * NN + (row & 15)) * D + k);
    } else {
        row = (blockIdx.x - PACKW_BLKS) * 4 + grp;
        w = *(const float4*)(x + (size_t)row * D + k);
    }

    float m = fmaxf(fmaxf(fabsf(w.x), fabsf(w.y)), fmaxf(fabsf(w.z), fabsf(w.w)));
#pragma unroll
    for (int off = 16; off >= 1; off >>= 1)
        m = fmaxf(m, __shfl_xor_sync(0xffffffffu, m, off));
    if (lane == 0) wmax[warp] = m;
    __syncthreads();
    float mm = fmaxf(wmax[grp * 2], wmax[grp * 2 + 1]);
    float scale = fmaxf(mm, 1e-20f) * (1.0f / 127.0f);
    float inv = 127.0f / fmaxf(mm, 1e-20f);

    __half h[4] = {__float2half_rn(w.x), __float2half_rn(w.y),
                   __float2half_rn(w.z), __float2half_rn(w.w)};
    char4 c = make_char4(q8(w.x, inv), q8(w.y, inv), q8(w.z, inv), q8(w.w, inv));

    if (isW) {
        if ((tid & 63) == 0) g_sw[row] = scale;
        *(ushort4*)(g_A + (size_t)row * KA + k) = *(ushort4*)h;
        *(char4*)(g_A8 + (size_t)row * D + k) = c;
    } else {
        if ((tid & 63) == 0) g_sx[row] = scale;
        *(ushort4*)(g_B + (size_t)row * D + k) = *(ushort4*)h;
        *(char4*)(g_B8 + (size_t)row * D + k) = c;
    }
}

// ---------------- int8 GEMM (mma.s8 m16n8k32) + traversal ----------------
#define GM 128
#define GN 128
#define GKB 128                            // k-BYTES per chunk
#define NSTAGE 2
#define NCH (D / GKB)                      // 2 chunks
#define STRA8 144                          // padded smem row bytes (128 + 16)

#define A_BYTES8 (GM * STRA8)              // 18432
#define STAGE_BYTES (2 * A_BYTES8)         // 36864 (A + B)
#define SC_LD 132                          // int32 scores, 128 cols + 4 pad
// score bytes = 128*132*4 = 67584 <= 2*STAGE_BYTES = 73728  OK (post-mainloop overlay)
#define OFF_AUX (NSTAGE * STAGE_BYTES)     // 73728
#define SMEM_TOTAL (OFF_AUX + 3 * 512 + 64)  // 75328 -> 2 CTA/SM

__global__ __launch_bounds__(256, 2)
void k_forest(const float* __restrict__ node_w, const float* __restrict__ node_b,
              const float* __restrict__ x) {
    extern __shared__ char sm[];
    const uint32_t sbase = smem_u32(sm);
    const int tid  = threadIdx.x;
    const int wid  = tid >> 5;
    const int lane = tid & 31;
    const int m0 = blockIdx.x * GM;
    const int n0 = blockIdx.y * GN;
    const int T0 = m0 >> 4;                // first tree (8 per tile)

    int*   sci = (int*)sm;                 // int32 scores (after mainloop)
    float* sb  = (float*)(sm + OFF_AUX);          // biases: 8 trees x 16 nodes
    float* swl = (float*)(sm + OFF_AUX + 512);    // W-row scales (128)
    float* sxs = (float*)(sm + OFF_AUX + 1024);   // sample scales (128)

    if (tid < 128) {
        int tree = T0 + (tid >> 4);
        sb[tid]  = (tree < T_TREES) ? node_b[tree * NN + (tid & 15)] : 0.f;
        swl[tid] = g_sw[m0 + tid];
        sxs[tid] = g_sx[n0 + tid];
    }

    auto load_chunk = [&](int c, int stg) {
        const uint32_t sA = sbase + stg * STAGE_BYTES;
        const uint32_t sB = sA + A_BYTES8;
        const int k0 = c * GKB;
#pragma unroll
        for (int r = 0; r < 4; r++) {      // A: 128 rows x 8 x 16B
            int op = tid + 256 * r;
            int row = op >> 3, q = op & 7;
            cp16(sA + (uint32_t)(row * STRA8 + q * 16),
                 g_A8 + (size_t)(m0 + row) * D + k0 + q * 16);
        }
#pragma unroll
        for (int r = 0; r < 4; r++) {      // B: 128 rows x 8 x 16B
            int op = tid + 256 * r;
            int row = op >> 3, q = op & 7;
            cp16(sB + (uint32_t)(row * STRA8 + q * 16),
                 g_B8 + (size_t)(n0 + row) * D + k0 + q * 16);
        }
        cp_commit();
    };

    load_chunk(0, 0); load_chunk(1, 1);

    // warp tiling: 2 (M) x 4 (N) warps, warp tile 64x32
    const int m0w = (wid & 1) * 64;
    const int n0w = (wid >> 1) * 32;
    // byte addresses; 16B segments = 16 k-bytes
    const int aBase = (m0w + (lane & 15)) * STRA8 + (lane >> 4) * 16;
    const int bBase = (n0w + (lane & 7) + ((lane >> 4) << 3)) * STRA8
                      + ((lane >> 3) & 1) * 16;

    int acc[4][4][4];
#pragma unroll
    for (int i = 0; i < 4; i++)
#pragma unroll
        for (int j = 0; j < 4; j++)
#pragma unroll
            for (int q = 0; q < 4; q++) acc[i][j][q] = 0;

    for (int c = 0; c < NCH; c++) {
        const int stg = c % NSTAGE;
        cp_wait<NSTAGE - 1>();
        __syncthreads();
        const uint32_t sA = sbase + stg * STAGE_BYTES;
        const uint32_t sB = sA + A_BYTES8;

        // A double-buffered across the 4 k32-steps; B loaded per step
        uint32_t af[2][4][4], bf[2][4];
#pragma unroll
        for (int mt = 0; mt < 4; mt++)
            ldsm4(af[0][mt], sA + (uint32_t)(aBase + mt * 16 * STRA8));

#pragma unroll
        for (int s = 0; s < 4; s++) {
            const int kk = s * 32;          // 32 k-bytes per step
            const int cur = s & 1, nxt = cur ^ 1;
#pragma unroll
            for (int j = 0; j < 2; j++)     // B: 2 x ldsm.x4 covers n32 x k32
                ldsm4(bf[j], sB + (uint32_t)(bBase + j * 16 * STRA8 + kk));
            if (s < 3) {
#pragma unroll
                for (int mt = 0; mt < 4; mt++)
                    ldsm4(af[nxt][mt],
                          sA + (uint32_t)(aBase + mt * 16 * STRA8 + kk + 32));
            }
#pragma unroll
            for (int mt = 0; mt < 4; mt++)
#pragma unroll
                for (int nt = 0; nt < 4; nt++)
                    mma_s8(acc[mt][nt], af[cur][mt], &bf[nt >> 1][(nt & 1) * 2]);
        }
        __syncthreads();
        if (c + NSTAGE < NCH) load_chunk(c + NSTAGE, stg);
        else cp_commit();
    }

    // ---- int32 scores to smem (overlay both stages) ----
#pragma unroll
    for (int mt = 0; mt < 4; mt++) {
        int row = m0w + mt * 16 + (lane >> 2);
#pragma unroll
        for (int nt = 0; nt < 4; nt++) {
            int nloc = n0w + nt * 8 + (lane & 3) * 2;
            *(int2*)(sci + row * SC_LD + nloc) = make_int2(acc[mt][nt][0], acc[mt][nt][1]);
            *(int2*)(sci + (row + 8) * SC_LD + nloc) = make_int2(acc[mt][nt][2], acc[mt][nt][3]);
        }
    }
    __syncthreads();

    // ---- traversal with 3-tier precision (int8 -> fp16 -> fp32) ----
#pragma unroll
    for (int task = tid; task < 1024; task += 256) {
        int tt = task >> 7, s = task & 127;
        int tree = T0 + tt;
        if (tree < T_TREES) {
            int sample = n0 + s;
            float sx = sxs[s];
            int idx = 0;
#pragma unroll
            for (int l = 0; l < 5; l++) {
                int node = (tt << 4) + idx;
                float z = (float)sci[node * SC_LD + s] * (swl[node] * sx) + sb[node];
                if (fabsf(z) < TAU8) {             // ~10% of decisions
                    z = dot16(m0 + node, sample) + sb[node];
                    if (fabsf(z) < TAU16)          // ~0.25% of refinements
                        z = exact_dot(node_w, x, tree, idx, sample) + sb[node];
                }
                idx = 2 * idx + (z <= 0.0f ? 1 : 0);
            }
            g_leaf[(size_t)tree * BATCH + sample] = (uint8_t)idx;
        }
    }
}

// ---------------- leaf gather + forest mean (R9 layout) ----------------
#define GSS 16
__global__ __launch_bounds__(256, 6)
void k_gather(const float* __restrict__ leaves, float* __restrict__ out) {
    __shared__ uint8_t sidx[T_TREES * GSS];
    const int s0  = blockIdx.x * GSS;
    const int tid = threadIdx.x;

    for (int i = tid; i < T_TREES * GSS / 4; i += 256) {
        int t = i >> 2, w = i & 3;
        ((uint32_t*)sidx)[i] =
            *(const uint32_t*)(g_leaf + (size_t)t * BATCH + s0 + w * 4);
    }
    __syncthreads();

    const int s = tid >> 4;      // 16 samples
    const int q = tid & 15;      // 16 class-quads (full 64 classes)
    float4 a = make_float4(0.f, 0.f, 0.f, 0.f);

#pragma unroll 4
    for (int t = 0; t < T_TREES; t++) {
        int idx = sidx[t * GSS + s];
        float4 v = *(const float4*)(leaves +
            ((size_t)(t * NLEAF + idx)) * NC + q * 4);
        a.x += v.x; a.y += v.y; a.z += v.z; a.w += v.w;
    }
    const float scl = 1.0f / (float)T_TREES;
    *(float4*)(out + (size_t)(s0 + s) * NC + q * 4) =
        make_float4(a.x * scl, a.y * scl, a.z * scl, a.w * scl);
}

// ---------------- launch ----------------
extern "C" void kernel_launch(void* const* d_in, const int* in_sizes, int n_in,
                              void* d_out, int out_size) {
    const float* x      = (const float*)d_in[0];   // [8192,256]
    const float* node_w = (const float*)d_in[1];   // [100,31,256]
    const float* node_b = (const float*)d_in[2];   // [100,31]
    const float* leaves = (const float*)d_in[3];   // [100,32,64]
    float* out = (float*)d_out;                    // [8192,64]

    k_pack<<<PACKW_BLKS + PACKX_BLKS, 256>>>(node_w, x);

    cudaFuncSetAttribute(k_forest, cudaFuncAttributeMaxDynamicSharedMemorySize,
                         SMEM_TOTAL);
    k_forest<<<dim3(MROWS / GM, BATCH / GN), 256, SMEM_TOTAL>>>(node_w, node_b, x);

    k_gather<<<BATCH / GSS, 256>>>(leaves, out);
}

// round 16
// speedup vs baseline: 2.0608x; 2.0608x over previous
#include <cuda_runtime.h>
#include <cuda_fp16.h>
#include <cstdint>

#define T_TREES 100
#define NN      31
#define D       256
#define BATCH   8192
#define NU      16
#define NLEAF   32
#define NC      64

#define MROWS   1664              // 13 * 128 (1600 used, rest zero)
#define KA      256
#define TAU8    1.5f              // int8 ambiguity band (~10 sigma of quant noise)
#define TAU16   0.05f             // fp16 ambiguity band (~8 sigma, validated)

// ---------------- static scratch ----------------
__device__ __align__(256) __half g_A[MROWS * KA];     // fp16 W (refine tier)
__device__ __align__(256) __half g_B[BATCH * D];      // fp16 X (refine tier)
__device__ __align__(256) char   g_A8[MROWS * D];     // int8 W
__device__ __align__(256) char   g_B8[BATCH * D];     // int8 X
__device__ float g_sw[MROWS];                         // per-W-row scale (max/127)
__device__ float g_sx[BATCH];                         // per-X-row scale
__device__ uint8_t g_leaf[T_TREES * BATCH];

// ---------------- helpers ----------------
__device__ __forceinline__ uint32_t smem_u32(const void* p) {
    uint32_t a;
    asm("{ .reg .u64 t; cvta.to.shared.u64 t, %1; cvt.u32.u64 %0, t; }"
        : "=r"(a) : "l"(p));
    return a;
}
__device__ __forceinline__ void cp16(uint32_t dst, const void* src) {
    asm volatile("cp.async.cg.shared.global [%0], [%1], 16;\n" :: "r"(dst), "l"(src));
}
__device__ __forceinline__ void cp_commit() { asm volatile("cp.async.commit_group;\n"); }
template <int N> __device__ __forceinline__ void cp_wait() {
    asm volatile("cp.async.wait_group %0;\n" :: "n"(N));
}
__device__ __forceinline__ void ldsm4(uint32_t* r, uint32_t addr) {
    asm volatile("ldmatrix.sync.aligned.m8n8.x4.shared.b16 {%0,%1,%2,%3}, [%4];"
        : "=r"(r[0]), "=r"(r[1]), "=r"(r[2]), "=r"(r[3]) : "r"(addr));
}
__device__ __forceinline__ void mma_s8(int* d, const uint32_t* a, const uint32_t* b) {
    asm volatile(
        "mma.sync.aligned.m16n8k32.row.col.s32.s8.s8.s32 "
        "{%0,%1,%2,%3}, {%4,%5,%6,%7}, {%8,%9}, {%0,%1,%2,%3};"
        : "+r"(d[0]), "+r"(d[1]), "+r"(d[2]), "+r"(d[3])
        : "r"(a[0]), "r"(a[1]), "r"(a[2]), "r"(a[3]), "r"(b[0]), "r"(b[1]));
}

// ---------------- merged pack kernel (scale + fp16 + int8 in one pass) -------
#define PACKW_BLKS (MROWS / 4)            // 416
#define PACKX_BLKS (BATCH / 4)            // 2048
__device__ __forceinline__ char q8(float v, float inv) {
    int q = __float2int_rn(v * inv);
    q = max(-127, min(127, q));
    return (char)q;
}
__global__ void k_pack(const float* __restrict__ node_w, const float* __restrict__ x) {
    __shared__ float wmax[8];
    const int tid  = threadIdx.x;
    const int warp = tid >> 5, lane = tid & 31;
    const int k = (tid & 63) * 4;
    const int grp = tid >> 6;              // row group 0..3

    float4 w = make_float4(0.f, 0.f, 0.f, 0.f);
    int row;
    bool isW = blockIdx.x < PACKW_BLKS;
    if (isW) {
        row = blockIdx.x * 4 + grp;
        int tree = row >> 4;
        if (tree < T_TREES)
            w = *(const float4*)(node_w + (size_t)(tree * NN + (row & 15)) * D + k);
    } else {
        row = (blockIdx.x - PACKW_BLKS) * 4 + grp;
        w = *(const float4*)(x + (size_t)row * D + k);
    }

    float m = fmaxf(fmaxf(fabsf(w.x), fabsf(w.y)), fmaxf(fabsf(w.z), fabsf(w.w)));
#pragma unroll
    for (int off = 16; off >= 1; off >>= 1)
        m = fmaxf(m, __shfl_xor_sync(0xffffffffu, m, off));
    if (lane == 0) wmax[warp] = m;
    __syncthreads();
    float mm = fmaxf(wmax[grp * 2], wmax[grp * 2 + 1]);
    float scale = fmaxf(mm, 1e-20f) * (1.0f / 127.0f);
    float inv = 127.0f / fmaxf(mm, 1e-20f);

    __half h[4] = {__float2half_rn(w.x), __float2half_rn(w.y),
                   __float2half_rn(w.z), __float2half_rn(w.w)};
    char4 c = make_char4(q8(w.x, inv), q8(w.y, inv), q8(w.z, inv), q8(w.w, inv));

    if (isW) {
        if ((tid & 63) == 0) g_sw[row] = scale;
        *(ushort4*)(g_A + (size_t)row * KA + k) = *(ushort4*)h;
        *(char4*)(g_A8 + (size_t)row * D + k) = c;
    } else {
        if ((tid & 63) == 0) g_sx[row] = scale;
        *(ushort4*)(g_B + (size_t)row * D + k) = *(ushort4*)h;
        *(char4*)(g_B8 + (size_t)row * D + k) = c;
    }
}

// ---------------- int8 GEMM (mma.s8 m16n8k32) + traversal ----------------
#define GM 128
#define GN 128
#define GKB 128                            // k-BYTES per chunk
#define NSTAGE 2
#define NCH (D / GKB)                      // 2 chunks
#define STRA8 144                          // padded smem row bytes (128 + 16)

#define A_BYTES8 (GM * STRA8)              // 18432
#define STAGE_BYTES (2 * A_BYTES8)         // 36864 (A + B)
#define SC_LD 132                          // int32 scores, 128 cols + 4 pad
#define OFF_AUX (NSTAGE * STAGE_BYTES)     // 73728
#define SMEM_TOTAL (OFF_AUX + 3 * 512 + 64)  // 75328 -> 2 CTA/SM

__global__ __launch_bounds__(256, 2)
void k_forest(const float* __restrict__ node_w, const float* __restrict__ node_b,
              const float* __restrict__ x) {
    extern __shared__ char sm[];
    const uint32_t sbase = smem_u32(sm);
    const int tid  = threadIdx.x;
    const int wid  = tid >> 5;
    const int lane = tid & 31;
    const int m0 = blockIdx.x * GM;
    const int n0 = blockIdx.y * GN;
    const int T0 = m0 >> 4;                // first tree (8 per tile)

    int*   sci = (int*)sm;                 // int32 scores (after mainloop)
    float* sb  = (float*)(sm + OFF_AUX);          // biases: 8 trees x 16 nodes
    float* swl = (float*)(sm + OFF_AUX + 512);    // W-row scales (128)
    float* sxs = (float*)(sm + OFF_AUX + 1024);   // sample scales (128)

    if (tid < 128) {
        int tree = T0 + (tid >> 4);
        sb[tid]  = (tree < T_TREES) ? node_b[tree * NN + (tid & 15)] : 0.f;
        swl[tid] = g_sw[m0 + tid];
        sxs[tid] = g_sx[n0 + tid];
    }

    auto load_chunk = [&](int c, int stg) {
        const uint32_t sA = sbase + stg * STAGE_BYTES;
        const uint32_t sB = sA + A_BYTES8;
        const int k0 = c * GKB;
#pragma unroll
        for (int r = 0; r < 4; r++) {      // A: 128 rows x 8 x 16B
            int op = tid + 256 * r;
            int row = op >> 3, q = op & 7;
            cp16(sA + (uint32_t)(row * STRA8 + q * 16),
                 g_A8 + (size_t)(m0 + row) * D + k0 + q * 16);
        }
#pragma unroll
        for (int r = 0; r < 4; r++) {      // B: 128 rows x 8 x 16B
            int op = tid + 256 * r;
            int row = op >> 3, q = op & 7;
            cp16(sB + (uint32_t)(row * STRA8 + q * 16),
                 g_B8 + (size_t)(n0 + row) * D + k0 + q * 16);
        }
        cp_commit();
    };

    load_chunk(0, 0); load_chunk(1, 1);

    // warp tiling: 2 (M) x 4 (N) warps, warp tile 64x32
    const int m0w = (wid & 1) * 64;
    const int n0w = (wid >> 1) * 32;
    const int aBase = (m0w + (lane & 15)) * STRA8 + (lane >> 4) * 16;
    const int bBase = (n0w + (lane & 7) + ((lane >> 4) << 3)) * STRA8
                      + ((lane >> 3) & 1) * 16;

    int acc[4][4][4];
#pragma unroll
    for (int i = 0; i < 4; i++)
#pragma unroll
        for (int j = 0; j < 4; j++)
#pragma unroll
            for (int q = 0; q < 4; q++) acc[i][j][q] = 0;

    for (int c = 0; c < NCH; c++) {
        const int stg = c % NSTAGE;
        cp_wait<NSTAGE - 1>();
        __syncthreads();
        const uint32_t sA = sbase + stg * STAGE_BYTES;
        const uint32_t sB = sA + A_BYTES8;

        uint32_t af[2][4][4], bf[2][4];
#pragma unroll
        for (int mt = 0; mt < 4; mt++)
            ldsm4(af[0][mt], sA + (uint32_t)(aBase + mt * 16 * STRA8));

#pragma unroll
        for (int s = 0; s < 4; s++) {
            const int kk = s * 32;          // 32 k-bytes per step
            const int cur = s & 1, nxt = cur ^ 1;
#pragma unroll
            for (int j = 0; j < 2; j++)
                ldsm4(bf[j], sB + (uint32_t)(bBase + j * 16 * STRA8 + kk));
            if (s < 3) {
#pragma unroll
                for (int mt = 0; mt < 4; mt++)
                    ldsm4(af[nxt][mt],
                          sA + (uint32_t)(aBase + mt * 16 * STRA8 + kk + 32));
            }
#pragma unroll
            for (int mt = 0; mt < 4; mt++)
#pragma unroll
                for (int nt = 0; nt < 4; nt++)
                    mma_s8(acc[mt][nt], af[cur][mt], &bf[nt >> 1][(nt & 1) * 2]);
        }
        __syncthreads();
        if (c + NSTAGE < NCH) load_chunk(c + NSTAGE, stg);
        else cp_commit();
    }

    // ---- int32 scores to smem (overlay both stages) ----
#pragma unroll
    for (int mt = 0; mt < 4; mt++) {
        int row = m0w + mt * 16 + (lane >> 2);
#pragma unroll
        for (int nt = 0; nt < 4; nt++) {
            int nloc = n0w + nt * 8 + (lane & 3) * 2;
            *(int2*)(sci + row * SC_LD + nloc) = make_int2(acc[mt][nt][0], acc[mt][nt][1]);
            *(int2*)(sci + (row + 8) * SC_LD + nloc) = make_int2(acc[mt][nt][2], acc[mt][nt][3]);
        }
    }
    __syncthreads();

    // ---- traversal with warp-cooperative ballot refinement ----
#pragma unroll
    for (int it = 0; it < 4; it++) {
        int task = tid + 256 * it;
        int tt = task >> 7, s = task & 127;
        int tree = T0 + tt;
        bool valid = tree < T_TREES;
        int sample = n0 + s;
        float sx = sxs[s];
        int idx = 0;
#pragma unroll
        for (int l = 0; l < 5; l++) {
            int node = (tt << 4) + idx;
            float z = (float)sci[node * SC_LD + s] * (swl[node] * sx) + sb[node];
            // ballot lanes whose |z| is inside the int8 ambiguity band
            unsigned mask = __ballot_sync(0xffffffffu, valid && fabsf(z) < TAU8);
            while (mask) {                 // cooperative: one dot at a time
                int src = __ffs(mask) - 1; mask &= mask - 1;
                int rn = __shfl_sync(0xffffffffu, node, src);
                int rs = __shfl_sync(0xffffffffu, sample, src);
                // fp16 tier: lane covers 8 contiguous halfs (coalesced 16B)
                uint4 wv = *(const uint4*)(g_A + (size_t)(m0 + rn) * KA + lane * 8);
                uint4 xv = *(const uint4*)(g_B + (size_t)rs * D + lane * 8);
                const __half2* wh = (const __half2*)&wv;
                const __half2* xh = (const __half2*)&xv;
                float p = 0.f;
#pragma unroll
                for (int j = 0; j < 4; j++) {
                    float2 a = __half22float2(wh[j]);
                    float2 b = __half22float2(xh[j]);
                    p += a.x * b.x + a.y * b.y;
                }
#pragma unroll
                for (int off = 16; off >= 1; off >>= 1)
                    p += __shfl_xor_sync(0xffffffffu, p, off);
                float zz = p + sb[rn];
                if (fabsf(zz) < TAU16) {   // fp32 tier (rare): lane covers 8 floats
                    int rt = T0 + (rn >> 4), rnode = rn & 15;
                    const float4* wp = (const float4*)(node_w +
                        (size_t)(rt * NN + rnode) * D);
                    const float4* xp = (const float4*)(x + (size_t)rs * D);
                    float4 w0 = wp[lane * 2], w1 = wp[lane * 2 + 1];
                    float4 x0 = xp[lane * 2], x1 = xp[lane * 2 + 1];
                    float p2 = w0.x * x0.x + w0.y * x0.y + w0.z * x0.z + w0.w * x0.w
                             + w1.x * x1.x + w1.y * x1.y + w1.z * x1.z + w1.w * x1.w;
#pragma unroll
                    for (int off = 16; off >= 1; off >>= 1)
                        p2 += __shfl_xor_sync(0xffffffffu, p2, off);
                    zz = p2 + sb[rn];
                }
                if (lane == src) z = zz;
            }
            idx = 2 * idx + (z <= 0.0f ? 1 : 0);
        }
        if (valid) g_leaf[(size_t)tree * BATCH + sample] = (uint8_t)idx;
    }
}

// ---------------- leaf gather + forest mean (R9 layout) ----------------
#define GSS 16
__global__ __launch_bounds__(256, 6)
void k_gather(const float* __restrict__ leaves, float* __restrict__ out) {
    __shared__ uint8_t sidx[T_TREES * GSS];
    const int s0  = blockIdx.x * GSS;
    const int tid = threadIdx.x;

    for (int i = tid; i < T_TREES * GSS / 4; i += 256) {
        int t = i >> 2, w = i & 3;
        ((uint32_t*)sidx)[i] =
            *(const uint32_t*)(g_leaf + (size_t)t * BATCH + s0 + w * 4);
    }
    __syncthreads();

    const int s = tid >> 4;      // 16 samples
    const int q = tid & 15;      // 16 class-quads (full 64 classes)
    float4 a = make_float4(0.f, 0.f, 0.f, 0.f);

#pragma unroll 4
    for (int t = 0; t < T_TREES; t++) {
        int idx = sidx[t * GSS + s];
        float4 v = *(const float4*)(leaves +
            ((size_t)(t * NLEAF + idx)) * NC + q * 4);
        a.x += v.x; a.y += v.y; a.z += v.z; a.w += v.w;
    }
    const float scl = 1.0f / (float)T_TREES;
    *(float4*)(out + (size_t)(s0 + s) * NC + q * 4) =
        make_float4(a.x * scl, a.y * scl, a.z * scl, a.w * scl);
}

// ---------------- launch ----------------
extern "C" void kernel_launch(void* const* d_in, const int* in_sizes, int n_in,
                              void* d_out, int out_size) {
    const float* x      = (const float*)d_in[0];   // [8192,256]
    const float* node_w = (const float*)d_in[1];   // [100,31,256]
    const float* node_b = (const float*)d_in[2];   // [100,31]
    const float* leaves = (const float*)d_in[3];   // [100,32,64]
    float* out = (float*)d_out;                    // [8192,64]

    k_pack<<<PACKW_BLKS + PACKX_BLKS, 256>>>(node_w, x);

    cudaFuncSetAttribute(k_forest, cudaFuncAttributeMaxDynamicSharedMemorySize,
                         SMEM_TOTAL);
    k_forest<<<dim3(MROWS / GM, BATCH / GN), 256, SMEM_TOTAL>>>(node_w, node_b, x);

    k_gather<<<BATCH / GSS, 256>>>(leaves, out);
}

// round 17
// speedup vs baseline: 2.1600x; 1.0482x over previous
#include <cuda_runtime.h>
#include <cuda_fp16.h>
#include <cstdint>

#define T_TREES 100
#define NN      31
#define D       256
#define BATCH   8192
#define NU      16
#define NLEAF   32
#define NC      64

#define MROWS   1664              // 13 * 128 (1600 used, rest zero)
#define KA      256
#define TAU8    1.2f              // int8 ambiguity band (~8 sigma of quant noise)
#define TAU16   0.05f             // fp16 ambiguity band (~8 sigma, validated)

// ---------------- static scratch ----------------
__device__ __align__(256) __half g_A[MROWS * KA];     // fp16 W (refine tier)
__device__ __align__(256) __half g_B[BATCH * D];      // fp16 X (refine tier)
__device__ __align__(256) char   g_A8[MROWS * D];     // int8 W
__device__ __align__(256) char   g_B8[BATCH * D];     // int8 X
__device__ float g_sw[MROWS];                         // per-W-row scale (max/127)
__device__ float g_sx[BATCH];                         // per-X-row scale
__device__ uint8_t g_leaf[T_TREES * BATCH];

// ---------------- helpers ----------------
__device__ __forceinline__ uint32_t smem_u32(const void* p) {
    uint32_t a;
    asm("{ .reg .u64 t; cvta.to.shared.u64 t, %1; cvt.u32.u64 %0, t; }"
        : "=r"(a) : "l"(p));
    return a;
}
__device__ __forceinline__ void cp16(uint32_t dst, const void* src) {
    asm volatile("cp.async.cg.shared.global [%0], [%1], 16;\n" :: "r"(dst), "l"(src));
}
__device__ __forceinline__ void cp_commit() { asm volatile("cp.async.commit_group;\n"); }
template <int N> __device__ __forceinline__ void cp_wait() {
    asm volatile("cp.async.wait_group %0;\n" :: "n"(N));
}
__device__ __forceinline__ void ldsm4(uint32_t* r, uint32_t addr) {
    asm volatile("ldmatrix.sync.aligned.m8n8.x4.shared.b16 {%0,%1,%2,%3}, [%4];"
        : "=r"(r[0]), "=r"(r[1]), "=r"(r[2]), "=r"(r[3]) : "r"(addr));
}
__device__ __forceinline__ void mma_s8(int* d, const uint32_t* a, const uint32_t* b) {
    asm volatile(
        "mma.sync.aligned.m16n8k32.row.col.s32.s8.s8.s32 "
        "{%0,%1,%2,%3}, {%4,%5,%6,%7}, {%8,%9}, {%0,%1,%2,%3};"
        : "+r"(d[0]), "+r"(d[1]), "+r"(d[2]), "+r"(d[3])
        : "r"(a[0]), "r"(a[1]), "r"(a[2]), "r"(a[3]), "r"(b[0]), "r"(b[1]));
}

// ---------------- merged pack kernel (scale + fp16 + int8 in one pass) -------
#define PACKW_BLKS (MROWS / 4)            // 416
#define PACKX_BLKS (BATCH / 4)            // 2048
__device__ __forceinline__ char q8(float v, float inv) {
    int q = __float2int_rn(v * inv);
    q = max(-127, min(127, q));
    return (char)q;
}
__global__ void k_pack(const float* __restrict__ node_w, const float* __restrict__ x) {
    __shared__ float wmax[8];
    const int tid  = threadIdx.x;
    const int warp = tid >> 5, lane = tid & 31;
    const int k = (tid & 63) * 4;
    const int grp = tid >> 6;              // row group 0..3

    float4 w = make_float4(0.f, 0.f, 0.f, 0.f);
    int row;
    bool isW = blockIdx.x < PACKW_BLKS;
    if (isW) {
        row = blockIdx.x * 4 + grp;
        int tree = row >> 4;
        if (tree < T_TREES)
            w = *(const float4*)(node_w + (size_t)(tree * NN + (row & 15)) * D + k);
    } else {
        row = (blockIdx.x - PACKW_BLKS) * 4 + grp;
        w = *(const float4*)(x + (size_t)row * D + k);
    }

    float m = fmaxf(fmaxf(fabsf(w.x), fabsf(w.y)), fmaxf(fabsf(w.z), fabsf(w.w)));
#pragma unroll
    for (int off = 16; off >= 1; off >>= 1)
        m = fmaxf(m, __shfl_xor_sync(0xffffffffu, m, off));
    if (lane == 0) wmax[warp] = m;
    __syncthreads();
    float mm = fmaxf(wmax[grp * 2], wmax[grp * 2 + 1]);
    float scale = fmaxf(mm, 1e-20f) * (1.0f / 127.0f);
    float inv = 127.0f / fmaxf(mm, 1e-20f);

    __half h[4] = {__float2half_rn(w.x), __float2half_rn(w.y),
                   __float2half_rn(w.z), __float2half_rn(w.w)};
    char4 c = make_char4(q8(w.x, inv), q8(w.y, inv), q8(w.z, inv), q8(w.w, inv));

    if (isW) {
        if ((tid & 63) == 0) g_sw[row] = scale;
        *(ushort4*)(g_A + (size_t)row * KA + k) = *(ushort4*)h;
        *(char4*)(g_A8 + (size_t)row * D + k) = c;
    } else {
        if ((tid & 63) == 0) g_sx[row] = scale;
        *(ushort4*)(g_B + (size_t)row * D + k) = *(ushort4*)h;
        *(char4*)(g_B8 + (size_t)row * D + k) = c;
    }
}

// ---------------- int8 GEMM (mma.s8 m16n8k32) + lockstep traversal ----------
#define GM 128
#define GN 128
#define GKB 128                            // k-BYTES per chunk
#define NSTAGE 2
#define NCH (D / GKB)                      // 2 chunks
#define STRA8 144                          // padded smem row bytes (128 + 16)

#define A_BYTES8 (GM * STRA8)              // 18432
#define STAGE_BYTES (2 * A_BYTES8)         // 36864 (A + B)
#define SC_LD 132                          // int32 scores, 128 cols + 4 pad
#define OFF_AUX (NSTAGE * STAGE_BYTES)     // 73728
#define SMEM_TOTAL (OFF_AUX + 3 * 512 + 64)  // 75328 -> 2 CTA/SM

__global__ __launch_bounds__(256, 2)
void k_forest(const float* __restrict__ node_w, const float* __restrict__ node_b,
              const float* __restrict__ x) {
    extern __shared__ char sm[];
    const uint32_t sbase = smem_u32(sm);
    const int tid  = threadIdx.x;
    const int wid  = tid >> 5;
    const int lane = tid & 31;
    const int m0 = blockIdx.x * GM;
    const int n0 = blockIdx.y * GN;
    const int T0 = m0 >> 4;                // first tree (8 per tile)

    int*   sci = (int*)sm;                 // int32 scores (after mainloop)
    float* sb  = (float*)(sm + OFF_AUX);          // biases: 8 trees x 16 nodes
    float* swl = (float*)(sm + OFF_AUX + 512);    // W-row scales (128)
    float* sxs = (float*)(sm + OFF_AUX + 1024);   // sample scales (128)

    if (tid < 128) {
        int tree = T0 + (tid >> 4);
        sb[tid]  = (tree < T_TREES) ? node_b[tree * NN + (tid & 15)] : 0.f;
        swl[tid] = g_sw[m0 + tid];
        sxs[tid] = g_sx[n0 + tid];
    }

    auto load_chunk = [&](int c, int stg) {
        const uint32_t sA = sbase + stg * STAGE_BYTES;
        const uint32_t sB = sA + A_BYTES8;
        const int k0 = c * GKB;
#pragma unroll
        for (int r = 0; r < 4; r++) {      // A: 128 rows x 8 x 16B
            int op = tid + 256 * r;
            int row = op >> 3, q = op & 7;
            cp16(sA + (uint32_t)(row * STRA8 + q * 16),
                 g_A8 + (size_t)(m0 + row) * D + k0 + q * 16);
        }
#pragma unroll
        for (int r = 0; r < 4; r++) {      // B: 128 rows x 8 x 16B
            int op = tid + 256 * r;
            int row = op >> 3, q = op & 7;
            cp16(sB + (uint32_t)(row * STRA8 + q * 16),
                 g_B8 + (size_t)(n0 + row) * D + k0 + q * 16);
        }
        cp_commit();
    };

    load_chunk(0, 0); load_chunk(1, 1);

    // warp tiling: 2 (M) x 4 (N) warps, warp tile 64x32
    const int m0w = (wid & 1) * 64;
    const int n0w = (wid >> 1) * 32;
    const int aBase = (m0w + (lane & 15)) * STRA8 + (lane >> 4) * 16;
    const int bBase = (n0w + (lane & 7) + ((lane >> 4) << 3)) * STRA8
                      + ((lane >> 3) & 1) * 16;

    int acc[4][4][4];
#pragma unroll
    for (int i = 0; i < 4; i++)
#pragma unroll
        for (int j = 0; j < 4; j++)
#pragma unroll
            for (int q = 0; q < 4; q++) acc[i][j][q] = 0;

    for (int c = 0; c < NCH; c++) {
        const int stg = c % NSTAGE;
        cp_wait<NSTAGE - 1>();
        __syncthreads();
        const uint32_t sA = sbase + stg * STAGE_BYTES;
        const uint32_t sB = sA + A_BYTES8;

        uint32_t af[2][4][4], bf[2][4];
#pragma unroll
        for (int mt = 0; mt < 4; mt++)
            ldsm4(af[0][mt], sA + (uint32_t)(aBase + mt * 16 * STRA8));

#pragma unroll
        for (int s = 0; s < 4; s++) {
            const int kk = s * 32;          // 32 k-bytes per step
            const int cur = s & 1, nxt = cur ^ 1;
#pragma unroll
            for (int j = 0; j < 2; j++)
                ldsm4(bf[j], sB + (uint32_t)(bBase + j * 16 * STRA8 + kk));
            if (s < 3) {
#pragma unroll
                for (int mt = 0; mt < 4; mt++)
                    ldsm4(af[nxt][mt],
                          sA + (uint32_t)(aBase + mt * 16 * STRA8 + kk + 32));
            }
#pragma unroll
            for (int mt = 0; mt < 4; mt++)
#pragma unroll
                for (int nt = 0; nt < 4; nt++)
                    mma_s8(acc[mt][nt], af[cur][mt], &bf[nt >> 1][(nt & 1) * 2]);
        }
        __syncthreads();
        if (c + NSTAGE < NCH) load_chunk(c + NSTAGE, stg);
        else cp_commit();
    }

    // ---- int32 scores to smem (overlay both stages) ----
#pragma unroll
    for (int mt = 0; mt < 4; mt++) {
        int row = m0w + mt * 16 + (lane >> 2);
#pragma unroll
        for (int nt = 0; nt < 4; nt++) {
            int nloc = n0w + nt * 8 + (lane & 3) * 2;
            *(int2*)(sci + row * SC_LD + nloc) = make_int2(acc[mt][nt][0], acc[mt][nt][1]);
            *(int2*)(sci + (row + 8) * SC_LD + nloc) = make_int2(acc[mt][nt][2], acc[mt][nt][3]);
        }
    }
    __syncthreads();

    // ---- lockstep traversal: 4 tasks/thread, batched 4-wide refinement ----
    int tts[4], lss[4], idxA[4];
    bool valids[4];
#pragma unroll
    for (int it = 0; it < 4; it++) {
        int task = tid + 256 * it;
        tts[it] = task >> 7; lss[it] = task & 127;
        valids[it] = (T0 + tts[it]) < T_TREES;
        idxA[it] = 0;
    }
    const int g = lane >> 3;               // refinement group 0..3
    const int j = lane & 7;                // position within group
    const unsigned gmask = 0xffu << (g * 8);

#pragma unroll
    for (int l = 0; l < 5; l++) {
        float z[4]; unsigned m[4]; uint32_t pk[4];
#pragma unroll
        for (int it = 0; it < 4; it++) {
            int node = (tts[it] << 4) + idxA[it];
            z[it] = (float)sci[node * SC_LD + lss[it]] * (swl[node] * sxs[lss[it]])
                    + sb[node];
            pk[it] = ((uint32_t)node << 16) | (uint32_t)lss[it];
        }
#pragma unroll
        for (int it = 0; it < 4; it++)
            m[it] = __ballot_sync(0xffffffffu, valids[it] && fabsf(z[it]) < TAU8);

        int cit = 0; unsigned cm = m[0];
        for (;;) {
            // collect up to 4 (lane, it) entries — warp-uniform schedule
            int bsrc[4], bitv[4], nb = 0;
            while (nb < 4) {
                if (cm == 0) { if (cit == 3) break; cit++; cm = m[cit]; continue; }
                bsrc[nb] = __ffs(cm) - 1; bitv[nb] = cit; cm &= cm - 1; nb++;
            }
            if (nb == 0) break;
            const int gg = g < nb ? g : nb - 1;
            // fetch packed (node|s) for entry gg
            uint32_t pv0 = __shfl_sync(0xffffffffu, pk[0], bsrc[gg]);
            uint32_t pv1 = __shfl_sync(0xffffffffu, pk[1], bsrc[gg]);
            uint32_t pv2 = __shfl_sync(0xffffffffu, pk[2], bsrc[gg]);
            uint32_t pv3 = __shfl_sync(0xffffffffu, pk[3], bsrc[gg]);
            uint32_t sel = (bitv[gg] == 0) ? pv0 : (bitv[gg] == 1) ? pv1
                         : (bitv[gg] == 2) ? pv2 : pv3;
            int rn = (int)(sel >> 16);         // node-row in tile (0..127)
            int rs = n0 + (int)(sel & 0xffffu);// global sample
            // fp16 tier: 8 lanes x 32 halfs, 8 independent 16B loads (MLP=8)
            const uint4* wp = (const uint4*)(g_A + (size_t)(m0 + rn) * KA) + j * 4;
            const uint4* xp = (const uint4*)(g_B + (size_t)rs * D) + j * 4;
            uint4 wv[4] = {wp[0], wp[1], wp[2], wp[3]};
            uint4 xv[4] = {xp[0], xp[1], xp[2], xp[3]};
            float p = 0.f;
#pragma unroll
            for (int q = 0; q < 4; q++) {
                const __half2* wh = (const __half2*)&wv[q];
                const __half2* xh = (const __half2*)&xv[q];
#pragma unroll
                for (int r = 0; r < 4; r++) {
                    float2 a = __half22float2(wh[r]);
                    float2 b = __half22float2(xh[r]);
                    p += a.x * b.x + a.y * b.y;
                }
            }
#pragma unroll
            for (int off = 4; off >= 1; off >>= 1)
                p += __shfl_xor_sync(0xffffffffu, p, off);
            float zz = p + sb[rn];
            if (fabsf(zz) < TAU16) {           // group-uniform; rare fp32 tier
                int rt = T0 + (rn >> 4), rnode = rn & 15;
                const float4* wp2 = (const float4*)(node_w +
                    (size_t)(rt * NN + rnode) * D) + j * 8;
                const float4* xp2 = (const float4*)(x + (size_t)rs * D) + j * 8;
                float p2 = 0.f;
#pragma unroll
                for (int q = 0; q < 8; q++) {
                    float4 a = wp2[q], b = xp2[q];
                    p2 += a.x * b.x + a.y * b.y + a.z * b.z + a.w * b.w;
                }
#pragma unroll
                for (int off = 4; off >= 1; off >>= 1)
                    p2 += __shfl_xor_sync(gmask, p2, off);
                zz = p2 + sb[rn];
            }
            // write back up to 4 refined scores
#pragma unroll
            for (int b = 0; b < 4; b++) {
                float v = __shfl_sync(0xffffffffu, zz, b * 8);
                if (b < nb && lane == bsrc[b]) z[bitv[b]] = v;
            }
        }
#pragma unroll
        for (int it = 0; it < 4; it++)
            idxA[it] = 2 * idxA[it] + (z[it] <= 0.0f ? 1 : 0);
    }
#pragma unroll
    for (int it = 0; it < 4; it++)
        if (valids[it])
            g_leaf[(size_t)(T0 + tts[it]) * BATCH + (n0 + lss[it])] = (uint8_t)idxA[it];
}

// ---------------- leaf gather + forest mean (R9 layout) ----------------
#define GSS 16
__global__ __launch_bounds__(256, 6)
void k_gather(const float* __restrict__ leaves, float* __restrict__ out) {
    __shared__ uint8_t sidx[T_TREES * GSS];
    const int s0  = blockIdx.x * GSS;
    const int tid = threadIdx.x;

    for (int i = tid; i < T_TREES * GSS / 4; i += 256) {
        int t = i >> 2, w = i & 3;
        ((uint32_t*)sidx)[i] =
            *(const uint32_t*)(g_leaf + (size_t)t * BATCH + s0 + w * 4);
    }
    __syncthreads();

    const int s = tid >> 4;      // 16 samples
    const int q = tid & 15;      // 16 class-quads (full 64 classes)
    float4 a = make_float4(0.f, 0.f, 0.f, 0.f);

#pragma unroll 4
    for (int t = 0; t < T_TREES; t++) {
        int idx = sidx[t * GSS + s];
        float4 v = *(const float4*)(leaves +
            ((size_t)(t * NLEAF + idx)) * NC + q * 4);
        a.x += v.x; a.y += v.y; a.z += v.z; a.w += v.w;
    }
    const float scl = 1.0f / (float)T_TREES;
    *(float4*)(out + (size_t)(s0 + s) * NC + q * 4) =
        make_float4(a.x * scl, a.y * scl, a.z * scl, a.w * scl);
}

// ---------------- launch ----------------
extern "C" void kernel_launch(void* const* d_in, const int* in_sizes, int n_in,
                              void* d_out, int out_size) {
    const float* x      = (const float*)d_in[0];   // [8192,256]
    const float* node_w = (const float*)d_in[1];   // [100,31,256]
    const float* node_b = (const float*)d_in[2];   // [100,31]
    const float* leaves = (const float*)d_in[3];   // [100,32,64]
    float* out = (float*)d_out;                    // [8192,64]

    k_pack<<<PACKW_BLKS + PACKX_BLKS, 256>>>(node_w, x);

    cudaFuncSetAttribute(k_forest, cudaFuncAttributeMaxDynamicSharedMemorySize,
                         SMEM_TOTAL);
    k_forest<<<dim3(MROWS / GM, BATCH / GN), 256, SMEM_TOTAL>>>(node_w, node_b, x);

    k_gather<<<BATCH / GSS, 256>>>(leaves, out);
}